// round 3
// baseline (speedup 1.0000x reference)
#include <cuda_runtime.h>

// YoloLoss: pred [B,7,7,30] f32, target [B,7,7,30] f32 -> scalar f32 loss.
// HBM-bound reduction: stage cells coalesced through smem, compute per-cell
// loss, hierarchical reduce, atomicAdd(double), finalize.

#define S7 7
#define CH 30
#define CPB 128          // cells per block == threads per block
#define SMEM_STRIDE 31   // 31 coprime with 32 -> conflict-free per-cell reads

__device__ double g_yolo_sum;

__global__ void yolo_zero_kernel() { g_yolo_sum = 0.0; }

__global__ void yolo_finalize_kernel(float* out, float invB) {
    out[0] = (float)(g_yolo_sum * (double)invB);
}

struct Box { float x1, y1, x2, y2; };

__device__ __forceinline__ Box convert_box(float x, float y, float w, float h,
                                           float gi, float gj) {
    const float STEPF = 1.0f / 7.0f;
    float cx = (x + gi) * STEPF;
    float cy = (y + gj) * STEPF;
    Box b;
    b.x1 = fmaxf(cx - w * 0.5f, 0.0f);
    b.y1 = fmaxf(cy - h * 0.5f, 0.0f);
    b.x2 = fminf(cx + w * 0.5f, 1.0f);
    b.y2 = fminf(cy + h * 0.5f, 1.0f);
    return b;
}

// b1 = target box (a,b,c,d), b2 = pred box (q,w,e,r) — matches reference arg order.
__device__ __forceinline__ float iou_ref(const Box& t, const Box& p) {
    float minx = fmaxf(t.x1, p.x1);
    float miny = fmaxf(t.y1, p.y1);
    float maxx = fminf(t.x2, p.x2);
    float maxy = fminf(t.y2, p.y2);
    float inter = (maxy - miny) * (maxx - minx);   // faithful: no clamp
    float uni = (p.x2 - p.x1) * (p.y2 - p.y1)
              + (t.x2 - t.x1) * (t.y2 - t.y1) - inter;
    return inter > 0.0f ? inter / (uni + 1e-5f) : 0.0f;
}

__global__ __launch_bounds__(CPB) void yolo_loss_kernel(
    const float* __restrict__ pred,
    const float* __restrict__ target,
    int ncells)
{
    __shared__ float sp[CPB * SMEM_STRIDE];
    __shared__ float st[CPB * SMEM_STRIDE];
    __shared__ float warp_part[CPB / 32];

    const int tid = threadIdx.x;
    const int cell0 = blockIdx.x * CPB;
    const int remaining = ncells - cell0;                 // cells this block owns
    const int nvalid = remaining < CPB ? remaining : CPB;
    const int base = cell0 * CH;
    const int nfloats = nvalid * CH;

    // Coalesced staging: consecutive threads read consecutive floats.
    #pragma unroll
    for (int i = 0; i < CH; i++) {
        int idx = i * CPB + tid;
        if (idx < nfloats) {
            int cell = idx / CH;
            int k = idx - cell * CH;
            sp[cell * SMEM_STRIDE + k] = pred[base + idx];
            st[cell * SMEM_STRIDE + k] = target[base + idx];
        }
    }
    __syncthreads();

    float loss = 0.0f;
    if (tid < nvalid) {
        const float* p = &sp[tid * SMEM_STRIDE];
        const float* t = &st[tid * SMEM_STRIDE];

        int cellg = cell0 + tid;
        int spatial = cellg % (S7 * S7);       // i*7 + j
        float gi = (float)(spatial / S7);      // first spatial axis -> x offset
        float gj = (float)(spatial % S7);      // second spatial axis -> y offset

        Box tb = convert_box(t[0], t[1], t[2], t[3], gi, gj);
        Box p1 = convert_box(p[0], p[1], p[2], p[3], gi, gj);
        Box p2 = convert_box(p[5], p[6], p[7], p[8], gi, gj);

        float iou1 = iou_ref(tb, p1);
        float iou2 = iou_ref(tb, p2);

        bool sel2 = (iou1 <= iou2);
        float conf_t = sel2 ? iou2 : iou1;
        float px = sel2 ? p[5] : p[0];
        float py = sel2 ? p[6] : p[1];
        float pw = sel2 ? p[7] : p[2];
        float ph = sel2 ? p[8] : p[3];
        float pconf = sel2 ? p[9] : p[4];

        float t4 = t[4];
        float obj   = (t4 > 0.0f)  ? 1.0f : 0.0f;
        float noobj = (t4 == 0.0f) ? 1.0f : 0.0f;

        float dx = px - t[0], dy = py - t[1];
        float dw = pw - t[2], dh = ph - t[3];
        float xywh = dx * dx + dy * dy + dw * dw + dh * dh;

        float dcls = 0.0f;
        #pragma unroll
        for (int k = 10; k < CH; k++) {
            float d = p[k] - t[k];
            dcls += d * d;
        }

        float dco = pconf - conf_t;
        float d4 = p[4] - t4;
        float d9 = p[9] - t[9];
        float dno = d4 * d4 + d9 * d9;

        loss = obj * (dco * dco) + 0.5f * noobj * dno
             + 5.0f * obj * xywh + obj * dcls;
    }

    // Warp reduce
    #pragma unroll
    for (int o = 16; o > 0; o >>= 1)
        loss += __shfl_xor_sync(0xffffffffu, loss, o);

    int lane = tid & 31;
    int wid = tid >> 5;
    if (lane == 0) warp_part[wid] = loss;
    __syncthreads();

    if (tid == 0) {
        float s = 0.0f;
        #pragma unroll
        for (int w = 0; w < CPB / 32; w++) s += warp_part[w];
        atomicAdd(&g_yolo_sum, (double)s);
    }
}

extern "C" void kernel_launch(void* const* d_in, const int* in_sizes, int n_in,
                              void* d_out, int out_size) {
    const float* pred = (const float*)d_in[0];
    const float* target = (const float*)d_in[1];
    float* out = (float*)d_out;

    int ncells = in_sizes[0] / CH;           // B * 7 * 7
    int B = ncells / (S7 * S7);

    yolo_zero_kernel<<<1, 1>>>();
    int blocks = (ncells + CPB - 1) / CPB;
    yolo_loss_kernel<<<blocks, CPB>>>(pred, target, ncells);
    yolo_finalize_kernel<<<1, 1>>>(out, 1.0f / (float)B);
}

// round 5
// speedup vs baseline: 1.0442x; 1.0442x over previous
#include <cuda_runtime.h>

// YoloLoss: pred [B,7,7,30] f32, target [B,7,7,30] f32 -> scalar f32 loss.
// Single-kernel HBM-bound reduction:
//   float4-coalesced staging -> smem -> per-cell loss -> block reduce ->
//   per-block partial (plain STG, no init needed) -> last block reduces all
//   partials and writes out. Ticket counter is reset by the winner, so the
//   kernel is replay-deterministic with no zeroing launch.

#define S7 7
#define CH 30
#define CPB 128                 // cells per block == threads per block
#define MAXBLK 8192

__device__ float g_partials[MAXBLK];
__device__ unsigned int g_ticket = 0;   // always returns to 0 after each launch

struct Box { float x1, y1, x2, y2; };

__device__ __forceinline__ Box convert_box(float x, float y, float w, float h,
                                           float gi, float gj) {
    const float STEPF = 1.0f / 7.0f;
    float cx = (x + gi) * STEPF;
    float cy = (y + gj) * STEPF;
    Box b;
    b.x1 = fmaxf(cx - w * 0.5f, 0.0f);
    b.y1 = fmaxf(cy - h * 0.5f, 0.0f);
    b.x2 = fminf(cx + w * 0.5f, 1.0f);
    b.y2 = fminf(cy + h * 0.5f, 1.0f);
    return b;
}

// t = target box, p = pred box — matches reference _iou(tbox, pbox) arg order.
__device__ __forceinline__ float iou_ref(const Box& t, const Box& p) {
    float minx = fmaxf(t.x1, p.x1);
    float miny = fmaxf(t.y1, p.y1);
    float maxx = fminf(t.x2, p.x2);
    float maxy = fminf(t.y2, p.y2);
    float inter = (maxy - miny) * (maxx - minx);   // faithful: no clamp
    float uni = (p.x2 - p.x1) * (p.y2 - p.y1)
              + (t.x2 - t.x1) * (t.y2 - t.y1) - inter;
    return inter > 0.0f ? inter / (uni + 1e-5f) : 0.0f;
}

__global__ __launch_bounds__(CPB) void yolo_loss_kernel(
    const float* __restrict__ pred,
    const float* __restrict__ target,
    int ncells, float invB, float* __restrict__ out)
{
    __shared__ float sp[CPB * CH];          // linear layout: aligned float4 stores
    __shared__ float st[CPB * CH];
    __shared__ float warp_part[CPB / 32];
    __shared__ int s_last;

    const int tid = threadIdx.x;
    const int bid = blockIdx.x;
    const int cell0 = bid * CPB;
    const int remaining = ncells - cell0;
    const int nvalid = remaining < CPB ? remaining : CPB;
    const int base = cell0 * CH;

    if (nvalid == CPB) {
        // Fast path: 960 float4 per tensor, fully coalesced 16B loads.
        // base floats = bid*3840 -> byte offset 15360*bid, 16B aligned.
        const float4* p4 = reinterpret_cast<const float4*>(pred + base);
        const float4* t4p = reinterpret_cast<const float4*>(target + base);
        float4* sp4 = reinterpret_cast<float4*>(sp);
        float4* st4 = reinterpret_cast<float4*>(st);
        const int n4 = CPB * CH / 4;        // 960
        #pragma unroll
        for (int i = 0; i < 8; i++) {
            int idx4 = i * CPB + tid;
            if (idx4 < n4) {
                sp4[idx4] = p4[idx4];
                st4[idx4] = t4p[idx4];
            }
        }
    } else {
        const int nfloats = nvalid * CH;
        for (int idx = tid; idx < nfloats; idx += CPB) {
            sp[idx] = pred[base + idx];
            st[idx] = target[base + idx];
        }
    }
    __syncthreads();

    float loss = 0.0f;
    if (tid < nvalid) {
        const float* p = &sp[tid * CH];
        const float* t = &st[tid * CH];

        int cellg = cell0 + tid;
        int spatial = cellg % (S7 * S7);       // i*7 + j
        float gi = (float)(spatial / S7);      // first spatial axis -> x offset
        float gj = (float)(spatial % S7);      // second spatial axis -> y offset

        Box tb = convert_box(t[0], t[1], t[2], t[3], gi, gj);
        Box p1 = convert_box(p[0], p[1], p[2], p[3], gi, gj);
        Box p2 = convert_box(p[5], p[6], p[7], p[8], gi, gj);

        float iou1 = iou_ref(tb, p1);
        float iou2 = iou_ref(tb, p2);

        bool sel2 = (iou1 <= iou2);
        float conf_t = sel2 ? iou2 : iou1;
        float px = sel2 ? p[5] : p[0];
        float py = sel2 ? p[6] : p[1];
        float pw = sel2 ? p[7] : p[2];
        float ph = sel2 ? p[8] : p[3];
        float pconf = sel2 ? p[9] : p[4];

        float tv4 = t[4];
        float obj   = (tv4 > 0.0f)  ? 1.0f : 0.0f;
        float noobj = (tv4 == 0.0f) ? 1.0f : 0.0f;

        float dx = px - t[0], dy = py - t[1];
        float dw = pw - t[2], dh = ph - t[3];
        float xywh = dx * dx + dy * dy + dw * dw + dh * dh;

        float dcls = 0.0f;
        #pragma unroll
        for (int k = 10; k < CH; k++) {
            float d = p[k] - t[k];
            dcls += d * d;
        }

        float dco = pconf - conf_t;
        float d4 = p[4] - tv4;
        float d9 = p[9] - t[9];
        float dno = d4 * d4 + d9 * d9;

        loss = obj * (dco * dco) + 0.5f * noobj * dno
             + 5.0f * obj * xywh + obj * dcls;
    }

    // Warp reduce, then block reduce.
    #pragma unroll
    for (int o = 16; o > 0; o >>= 1)
        loss += __shfl_xor_sync(0xffffffffu, loss, o);

    int lane = tid & 31;
    int wid = tid >> 5;
    if (lane == 0) warp_part[wid] = loss;
    __syncthreads();

    if (tid == 0) {
        float s = 0.0f;
        #pragma unroll
        for (int w = 0; w < CPB / 32; w++) s += warp_part[w];
        g_partials[bid] = s;                       // every slot written: no init needed
        __threadfence();
        unsigned int v = atomicAdd(&g_ticket, 1u);
        s_last = (v == gridDim.x - 1) ? 1 : 0;
    }
    __syncthreads();

    if (s_last) {
        // Last block to finish: reduce all per-block partials, write output.
        int nblk = gridDim.x;
        float acc = 0.0f;
        for (int i = tid; i < nblk; i += CPB)
            acc += g_partials[i];
        #pragma unroll
        for (int o = 16; o > 0; o >>= 1)
            acc += __shfl_xor_sync(0xffffffffu, acc, o);
        if (lane == 0) warp_part[wid] = acc;
        __syncthreads();
        if (tid == 0) {
            double total = 0.0;
            #pragma unroll
            for (int w = 0; w < CPB / 32; w++) total += (double)warp_part[w];
            out[0] = (float)(total * (double)invB);
            g_ticket = 0;                          // restore invariant for next replay
        }
    }
}

extern "C" void kernel_launch(void* const* d_in, const int* in_sizes, int n_in,
                              void* d_out, int out_size) {
    const float* pred = (const float*)d_in[0];
    const float* target = (const float*)d_in[1];
    float* out = (float*)d_out;

    int ncells = in_sizes[0] / CH;           // B * 7 * 7
    int B = ncells / (S7 * S7);
    int blocks = (ncells + CPB - 1) / CPB;   // 6272 for B=16384

    yolo_loss_kernel<<<blocks, CPB>>>(pred, target, ncells, 1.0f / (float)B, out);
}

// round 6
// speedup vs baseline: 1.2962x; 1.2413x over previous
#include <cuda_runtime.h>
#include <cstdint>

// YoloLoss: pred [B,7,7,30] f32, target [B,7,7,30] f32 -> scalar f32 loss.
// Persistent double-buffered cp.async pipeline:
//   each block loops over tiles of 128 cells; while computing tile t from
//   buffer A, tile t+1 streams into buffer B via cp.async (LDGSTS).
//   Per-thread loss accumulates across tiles; one block reduce at the end,
//   then per-block partial + ticket; last block reduces partials -> out.

#define S7 7
#define CH 30
#define CPB 128
#define TILE_FLOATS (CPB * CH)          // 3840 floats per tensor per tile
#define TILE_BYTES  (TILE_FLOATS * 4)   // 15360 B
#define BUF_FLOATS  (2 * TILE_FLOATS)   // pred + target per buffer
#define SMEM_BYTES  (2 * BUF_FLOATS * 4) // two buffers = 61440 B
#define NBLOCKS 444                     // 3 CTAs/SM * 148 SMs
#define MAXBLK 8192

__device__ float g_partials[MAXBLK];
__device__ unsigned int g_ticket = 0;   // returns to 0 after every launch

__device__ __forceinline__ uint32_t smem_u32(const void* p) {
    return (uint32_t)__cvta_generic_to_shared(p);
}
__device__ __forceinline__ void cp16(uint32_t dst, const void* src) {
    asm volatile("cp.async.cg.shared.global [%0], [%1], 16;\n" :: "r"(dst), "l"(src));
}
__device__ __forceinline__ void cp4(uint32_t dst, const void* src) {
    asm volatile("cp.async.ca.shared.global [%0], [%1], 4;\n" :: "r"(dst), "l"(src));
}
__device__ __forceinline__ void cp_commit() {
    asm volatile("cp.async.commit_group;\n");
}
__device__ __forceinline__ void cp_wait1() {
    asm volatile("cp.async.wait_group 1;\n" ::: "memory");
}
__device__ __forceinline__ void cp_wait0() {
    asm volatile("cp.async.wait_group 0;\n" ::: "memory");
}

struct Box { float x1, y1, x2, y2; };

__device__ __forceinline__ Box convert_box(float x, float y, float w, float h,
                                           float gi, float gj) {
    const float STEPF = 1.0f / 7.0f;
    float cx = (x + gi) * STEPF;
    float cy = (y + gj) * STEPF;
    Box b;
    b.x1 = fmaxf(cx - w * 0.5f, 0.0f);
    b.y1 = fmaxf(cy - h * 0.5f, 0.0f);
    b.x2 = fminf(cx + w * 0.5f, 1.0f);
    b.y2 = fminf(cy + h * 0.5f, 1.0f);
    return b;
}

// t = target box, p = pred box — matches reference _iou(tbox, pbox) arg order.
__device__ __forceinline__ float iou_ref(const Box& t, const Box& p) {
    float minx = fmaxf(t.x1, p.x1);
    float miny = fmaxf(t.y1, p.y1);
    float maxx = fminf(t.x2, p.x2);
    float maxy = fminf(t.y2, p.y2);
    float inter = (maxy - miny) * (maxx - minx);   // faithful: no clamp
    float uni = (p.x2 - p.x1) * (p.y2 - p.y1)
              + (t.x2 - t.x1) * (t.y2 - t.y1) - inter;
    return inter > 0.0f ? inter / (uni + 1e-5f) : 0.0f;
}

__device__ __forceinline__ void prefetch_tile(
    float* sbuf, const float* __restrict__ pred, const float* __restrict__ target,
    int tile, int ncells, int tid)
{
    int cell0 = tile * CPB;
    int nvalid = min(ncells - cell0, CPB);
    const char* pg = (const char*)(pred + (size_t)cell0 * CH);
    const char* tg = (const char*)(target + (size_t)cell0 * CH);
    uint32_t sp = smem_u32(sbuf);
    uint32_t st = sp + TILE_BYTES;
    if (nvalid == CPB) {
        // 960 float4 per tensor, fully coalesced 16B cp.async.
        #pragma unroll
        for (int i = 0; i < 8; i++) {
            int idx4 = i * CPB + tid;
            if (idx4 < TILE_FLOATS / 4) {
                cp16(sp + idx4 * 16, pg + idx4 * 16);
                cp16(st + idx4 * 16, tg + idx4 * 16);
            }
        }
    } else {
        int nf = nvalid * CH;
        for (int idx = tid; idx < nf; idx += CPB) {
            cp4(sp + idx * 4, pg + idx * 4);
            cp4(st + idx * 4, tg + idx * 4);
        }
    }
}

__device__ __forceinline__ float compute_tile(
    const float* sbuf, int tile, int ncells, int tid)
{
    int cell0 = tile * CPB;
    int nvalid = min(ncells - cell0, CPB);
    if (tid >= nvalid) return 0.0f;

    const float* p = sbuf + tid * CH;
    const float* t = sbuf + TILE_FLOATS + tid * CH;

    int cellg = cell0 + tid;
    int spatial = cellg % (S7 * S7);       // i*7 + j
    float gi = (float)(spatial / S7);      // first spatial axis -> x offset
    float gj = (float)(spatial % S7);      // second spatial axis -> y offset

    Box tb = convert_box(t[0], t[1], t[2], t[3], gi, gj);
    Box p1 = convert_box(p[0], p[1], p[2], p[3], gi, gj);
    Box p2 = convert_box(p[5], p[6], p[7], p[8], gi, gj);

    float iou1 = iou_ref(tb, p1);
    float iou2 = iou_ref(tb, p2);

    bool sel2 = (iou1 <= iou2);
    float conf_t = sel2 ? iou2 : iou1;
    float px = sel2 ? p[5] : p[0];
    float py = sel2 ? p[6] : p[1];
    float pw = sel2 ? p[7] : p[2];
    float ph = sel2 ? p[8] : p[3];
    float pconf = sel2 ? p[9] : p[4];

    float tv4 = t[4];
    float obj   = (tv4 > 0.0f)  ? 1.0f : 0.0f;
    float noobj = (tv4 == 0.0f) ? 1.0f : 0.0f;

    float dx = px - t[0], dy = py - t[1];
    float dw = pw - t[2], dh = ph - t[3];
    float xywh = dx * dx + dy * dy + dw * dw + dh * dh;

    float dcls = 0.0f;
    #pragma unroll
    for (int k = 10; k < CH; k++) {
        float d = p[k] - t[k];
        dcls += d * d;
    }

    float dco = pconf - conf_t;
    float d4 = p[4] - tv4;
    float d9 = p[9] - t[9];
    float dno = d4 * d4 + d9 * d9;

    return obj * (dco * dco) + 0.5f * noobj * dno
         + 5.0f * obj * xywh + obj * dcls;
}

extern __shared__ float dynsmem[];

__global__ __launch_bounds__(CPB) void yolo_loss_kernel(
    const float* __restrict__ pred,
    const float* __restrict__ target,
    int ncells, int ntiles, float invB, float* __restrict__ out)
{
    __shared__ float warp_part[CPB / 32];
    __shared__ int s_last;

    const int tid = threadIdx.x;
    const int bid = blockIdx.x;
    const int stride = gridDim.x;

    float* buf0 = dynsmem;
    float* buf1 = dynsmem + BUF_FLOATS;

    float acc = 0.0f;

    // Prologue: prefetch first tile.
    int t = bid;
    if (t < ntiles) prefetch_tile(buf0, pred, target, t, ncells, tid);
    cp_commit();

    int cur = 0;
    for (; t < ntiles; t += stride) {
        int tn = t + stride;
        bool more = (tn < ntiles);
        float* nbuf = cur ? buf0 : buf1;
        float* cbuf = cur ? buf1 : buf0;
        if (more) prefetch_tile(nbuf, pred, target, tn, ncells, tid);
        cp_commit();
        if (more) cp_wait1(); else cp_wait0();
        __syncthreads();                 // current tile fully visible to all
        acc += compute_tile(cbuf, t, ncells, tid);
        __syncthreads();                 // all done reading before buffer reuse
        cur ^= 1;
    }

    // Block reduce (once per block, not per tile).
    #pragma unroll
    for (int o = 16; o > 0; o >>= 1)
        acc += __shfl_xor_sync(0xffffffffu, acc, o);

    int lane = tid & 31;
    int wid = tid >> 5;
    if (lane == 0) warp_part[wid] = acc;
    __syncthreads();

    if (tid == 0) {
        float s = 0.0f;
        #pragma unroll
        for (int w = 0; w < CPB / 32; w++) s += warp_part[w];
        g_partials[bid] = s;                       // every slot written: no init needed
        __threadfence();
        unsigned int v = atomicAdd(&g_ticket, 1u);
        s_last = (v == gridDim.x - 1) ? 1 : 0;
    }
    __syncthreads();

    if (s_last) {
        int nblk = gridDim.x;
        float r = 0.0f;
        for (int i = tid; i < nblk; i += CPB)
            r += g_partials[i];
        #pragma unroll
        for (int o = 16; o > 0; o >>= 1)
            r += __shfl_xor_sync(0xffffffffu, r, o);
        if (lane == 0) warp_part[wid] = r;
        __syncthreads();
        if (tid == 0) {
            double total = 0.0;
            #pragma unroll
            for (int w = 0; w < CPB / 32; w++) total += (double)warp_part[w];
            out[0] = (float)(total * (double)invB);
            g_ticket = 0;                          // restore invariant for replays
        }
    }
}

extern "C" void kernel_launch(void* const* d_in, const int* in_sizes, int n_in,
                              void* d_out, int out_size) {
    const float* pred = (const float*)d_in[0];
    const float* target = (const float*)d_in[1];
    float* out = (float*)d_out;

    int ncells = in_sizes[0] / CH;                 // B * 7 * 7
    int B = ncells / (S7 * S7);
    int ntiles = (ncells + CPB - 1) / CPB;         // 6272 for B=16384

    static int attr_set = 0;
    if (!attr_set) {
        cudaFuncSetAttribute(yolo_loss_kernel,
                             cudaFuncAttributeMaxDynamicSharedMemorySize,
                             SMEM_BYTES);
        attr_set = 1;
    }

    yolo_loss_kernel<<<NBLOCKS, CPB, SMEM_BYTES>>>(
        pred, target, ncells, ntiles, 1.0f / (float)B, out);
}